// round 1
// baseline (speedup 1.0000x reference)
#include <cuda_runtime.h>

// Problem constants
#define T_LEN   8192
#define BATCH   4
#define D_MODEL 1024
#define NHEAD   16
#define HD      64
#define QKV_LD  (3 * D_MODEL)        // 3072
#define NROWS   (T_LEN * BATCH)      // 32768
#define NHEADS_TOTAL (BATCH * NHEAD) // 64

// Per-head stats layout: [0,4096) C[i][j], [4096,4160) Sq, [4160,4224) Sk,
// [4224,4288) Sqq, [4288,4352) Skk
#define STATS_PER_HEAD 4352

// Scratch (device globals: allocation-free)
__device__ float g_qkv[(size_t)NROWS * QKV_LD];                    // 384 MB
__device__ float g_meffT[(size_t)BATCH * D_MODEL * D_MODEL];       // 16 MB
__device__ float g_stats[NHEADS_TOTAL * STATS_PER_HEAD];
__device__ float g_corr[NHEADS_TOTAL * HD * HD];

// ---------------------------------------------------------------------------
// Zero the stats accumulator
// ---------------------------------------------------------------------------
__global__ void zero_stats_kernel() {
    int idx = blockIdx.x * blockDim.x + threadIdx.x;
    if (idx < NHEADS_TOTAL * STATS_PER_HEAD) g_stats[idx] = 0.0f;
}

// ---------------------------------------------------------------------------
// GEMM (NT): C[m,n] = sum_k A[m,k] * B[n,k] + bias[n]
// A rows strided by strideA; B rows contiguous length K; batched via blockIdx.z
// 128x128 tile, BK=16, 8x8 microtile, 256 threads, double-buffered smem.
// ---------------------------------------------------------------------------
#define GBM 128
#define GBN 128
#define GBK 16

__global__ __launch_bounds__(256, 2) void gemm_nt_kernel(
    const float* __restrict__ A, int strideA, long batchA,
    const float* __restrict__ B, long batchB,
    const float* __restrict__ bias,
    float* __restrict__ C, int strideC, long batchC,
    int K)
{
    __shared__ float As[2][GBK][GBM];
    __shared__ float Bs[2][GBK][GBN];

    const int z = blockIdx.z;
    A += (size_t)blockIdx.y * GBM * strideA + (size_t)z * batchA;
    B += (size_t)blockIdx.x * GBN * K + (size_t)z * batchB;
    C += (size_t)blockIdx.y * GBM * strideC + (size_t)blockIdx.x * GBN
         + (size_t)z * batchC;
    const float* biasp = bias + (size_t)blockIdx.x * GBN;

    const int tid  = threadIdx.x;
    const int arow0 = tid >> 2;          // 0..63
    const int arow1 = arow0 + 64;        // 64..127
    const int ak0   = (tid & 3) << 2;    // 0,4,8,12
    const int tx = tid & 15, ty = tid >> 4;
    const int m0 = ty * 8, n0 = tx * 8;

    float acc[8][8];
    #pragma unroll
    for (int i = 0; i < 8; i++)
        #pragma unroll
        for (int j = 0; j < 8; j++) acc[i][j] = 0.0f;

    // Preload tile 0
    float4 pa0 = *(const float4*)(A + (size_t)arow0 * strideA + ak0);
    float4 pa1 = *(const float4*)(A + (size_t)arow1 * strideA + ak0);
    float4 pb0 = *(const float4*)(B + (size_t)arow0 * K + ak0);
    float4 pb1 = *(const float4*)(B + (size_t)arow1 * K + ak0);

    As[0][ak0 + 0][arow0] = pa0.x; As[0][ak0 + 1][arow0] = pa0.y;
    As[0][ak0 + 2][arow0] = pa0.z; As[0][ak0 + 3][arow0] = pa0.w;
    As[0][ak0 + 0][arow1] = pa1.x; As[0][ak0 + 1][arow1] = pa1.y;
    As[0][ak0 + 2][arow1] = pa1.z; As[0][ak0 + 3][arow1] = pa1.w;
    Bs[0][ak0 + 0][arow0] = pb0.x; Bs[0][ak0 + 1][arow0] = pb0.y;
    Bs[0][ak0 + 2][arow0] = pb0.z; Bs[0][ak0 + 3][arow0] = pb0.w;
    Bs[0][ak0 + 0][arow1] = pb1.x; Bs[0][ak0 + 1][arow1] = pb1.y;
    Bs[0][ak0 + 2][arow1] = pb1.z; Bs[0][ak0 + 3][arow1] = pb1.w;
    __syncthreads();

    const int NKT = K / GBK;
    int buf = 0;
    for (int kt = 0; kt < NKT; kt++) {
        const bool pf = (kt + 1 < NKT);
        if (pf) {
            const float* Ap = A + (size_t)(kt + 1) * GBK;
            const float* Bp = B + (size_t)(kt + 1) * GBK;
            pa0 = *(const float4*)(Ap + (size_t)arow0 * strideA + ak0);
            pa1 = *(const float4*)(Ap + (size_t)arow1 * strideA + ak0);
            pb0 = *(const float4*)(Bp + (size_t)arow0 * K + ak0);
            pb1 = *(const float4*)(Bp + (size_t)arow1 * K + ak0);
        }
        #pragma unroll
        for (int k = 0; k < GBK; k++) {
            float4 a0 = *(const float4*)&As[buf][k][m0];
            float4 a1 = *(const float4*)&As[buf][k][m0 + 4];
            float4 b0 = *(const float4*)&Bs[buf][k][n0];
            float4 b1 = *(const float4*)&Bs[buf][k][n0 + 4];
            float af[8] = {a0.x, a0.y, a0.z, a0.w, a1.x, a1.y, a1.z, a1.w};
            float bfv[8] = {b0.x, b0.y, b0.z, b0.w, b1.x, b1.y, b1.z, b1.w};
            #pragma unroll
            for (int i = 0; i < 8; i++)
                #pragma unroll
                for (int j = 0; j < 8; j++)
                    acc[i][j] += af[i] * bfv[j];
        }
        if (pf) {
            const int nb = buf ^ 1;
            As[nb][ak0 + 0][arow0] = pa0.x; As[nb][ak0 + 1][arow0] = pa0.y;
            As[nb][ak0 + 2][arow0] = pa0.z; As[nb][ak0 + 3][arow0] = pa0.w;
            As[nb][ak0 + 0][arow1] = pa1.x; As[nb][ak0 + 1][arow1] = pa1.y;
            As[nb][ak0 + 2][arow1] = pa1.z; As[nb][ak0 + 3][arow1] = pa1.w;
            Bs[nb][ak0 + 0][arow0] = pb0.x; Bs[nb][ak0 + 1][arow0] = pb0.y;
            Bs[nb][ak0 + 2][arow0] = pb0.z; Bs[nb][ak0 + 3][arow0] = pb0.w;
            Bs[nb][ak0 + 0][arow1] = pb1.x; Bs[nb][ak0 + 1][arow1] = pb1.y;
            Bs[nb][ak0 + 2][arow1] = pb1.z; Bs[nb][ak0 + 3][arow1] = pb1.w;
        }
        __syncthreads();
        buf ^= 1;
    }

    // Epilogue (+ bias)
    float bv[8];
    #pragma unroll
    for (int j = 0; j < 8; j++) bv[j] = biasp[n0 + j];
    #pragma unroll
    for (int i = 0; i < 8; i++) {
        float4 o0, o1;
        o0.x = acc[i][0] + bv[0]; o0.y = acc[i][1] + bv[1];
        o0.z = acc[i][2] + bv[2]; o0.w = acc[i][3] + bv[3];
        o1.x = acc[i][4] + bv[4]; o1.y = acc[i][5] + bv[5];
        o1.z = acc[i][6] + bv[6]; o1.w = acc[i][7] + bv[7];
        *(float4*)(C + (size_t)(m0 + i) * strideC + n0)     = o0;
        *(float4*)(C + (size_t)(m0 + i) * strideC + n0 + 4) = o1;
    }
}

// ---------------------------------------------------------------------------
// Stats: per head (b,h) accumulate C[i][j]=sum_t q_i k_j, Sq, Sk, Sqq, Skk
// grid (TSPLIT, 64 heads), block 256. Atomic-accumulate into g_stats.
// ---------------------------------------------------------------------------
#define TSPLIT 8
#define TCHUNK (T_LEN / TSPLIT)   // 1024

__global__ __launch_bounds__(256) void stats_kernel(const float* __restrict__ qkv) {
    const int head = blockIdx.y;          // 0..63
    const int b = head >> 4, h = head & 15;
    const int tid = threadIdx.x;

    __shared__ float qs[16][HD];
    __shared__ float ks[16][HD];

    const float* qbase = qkv + (size_t)b * QKV_LD + h * HD;
    const float* kbase = qbase + D_MODEL;

    float acc[4][4];
    #pragma unroll
    for (int i = 0; i < 4; i++)
        #pragma unroll
        for (int j = 0; j < 4; j++) acc[i][j] = 0.0f;
    float sq = 0.f, sqq = 0.f, sk = 0.f, skk = 0.f;

    const int i0 = (tid >> 4) * 4, j0 = (tid & 15) * 4;
    const int lrow = tid >> 4;             // 0..15
    const int lcol = (tid & 15) * 4;       // 0..60

    const int tstart = blockIdx.x * TCHUNK;
    for (int t0 = tstart; t0 < tstart + TCHUNK; t0 += 16) {
        size_t grow = (size_t)(t0 + lrow) * BATCH * QKV_LD;
        *(float4*)&qs[lrow][lcol] = *(const float4*)(qbase + grow + lcol);
        *(float4*)&ks[lrow][lcol] = *(const float4*)(kbase + grow + lcol);
        __syncthreads();

        if (tid < 64) {
            #pragma unroll
            for (int tt = 0; tt < 16; tt++) {
                float v = qs[tt][tid]; sq += v; sqq += v * v;
            }
        } else if (tid < 128) {
            int j = tid - 64;
            #pragma unroll
            for (int tt = 0; tt < 16; tt++) {
                float v = ks[tt][j]; sk += v; skk += v * v;
            }
        }
        #pragma unroll
        for (int tt = 0; tt < 16; tt++) {
            float4 qa = *(const float4*)&qs[tt][i0];
            float4 kb = *(const float4*)&ks[tt][j0];
            float qv[4] = {qa.x, qa.y, qa.z, qa.w};
            float kv[4] = {kb.x, kb.y, kb.z, kb.w};
            #pragma unroll
            for (int ii = 0; ii < 4; ii++)
                #pragma unroll
                for (int jj = 0; jj < 4; jj++)
                    acc[ii][jj] += qv[ii] * kv[jj];
        }
        __syncthreads();
    }

    float* st = g_stats + (size_t)head * STATS_PER_HEAD;
    #pragma unroll
    for (int ii = 0; ii < 4; ii++)
        #pragma unroll
        for (int jj = 0; jj < 4; jj++)
            atomicAdd(&st[(i0 + ii) * HD + (j0 + jj)], acc[ii][jj]);
    if (tid < 64) {
        atomicAdd(&st[4096 + tid], sq);
        atomicAdd(&st[4224 + tid], sqq);
    } else if (tid < 128) {
        atomicAdd(&st[4160 + (tid - 64)], sk);
        atomicAdd(&st[4288 + (tid - 64)], skk);
    }
}

// ---------------------------------------------------------------------------
// Corr: corr = softmax_i(clip(cov/sqrt(sx*sy),0,1)). One block per head.
// ---------------------------------------------------------------------------
__global__ __launch_bounds__(256) void corr_kernel() {
    const int head = blockIdx.x;
    const int tid = threadIdx.x;
    __shared__ float sc[HD][HD + 1];
    __shared__ float mq[HD], mk[HD], isx[HD], isy[HD];

    const float* st = g_stats + (size_t)head * STATS_PER_HEAD;
    const float invT = 1.0f / (float)T_LEN;

    if (tid < 64) {
        float s = st[4096 + tid], s2 = st[4224 + tid];
        mq[tid] = s;
        isx[tid] = rsqrtf(s2 - s * s * invT);
    } else if (tid < 128) {
        int j = tid - 64;
        float s = st[4160 + j], s2 = st[4288 + j];
        mk[j] = s;
        isy[j] = rsqrtf(s2 - s * s * invT);
    }
    __syncthreads();

    for (int idx = tid; idx < HD * HD; idx += 256) {
        int i = idx >> 6, j = idx & 63;
        float cov = st[idx] - mq[i] * mk[j] * invT;
        float c = cov * isx[i] * isy[j];
        c = fminf(fmaxf(c, 0.0f), 1.0f);
        sc[i][j] = c;
    }
    __syncthreads();

    // softmax over i (rows) for each column j
    if (tid < 64) {
        int j = tid;
        float mx = -1e30f;
        #pragma unroll 4
        for (int i = 0; i < HD; i++) mx = fmaxf(mx, sc[i][j]);
        float sum = 0.f;
        #pragma unroll 4
        for (int i = 0; i < HD; i++) {
            float e = expf(sc[i][j] - mx);
            sc[i][j] = e; sum += e;
        }
        float inv = 1.0f / sum;
        #pragma unroll 4
        for (int i = 0; i < HD; i++) sc[i][j] *= inv;
    }
    __syncthreads();

    for (int idx = tid; idx < HD * HD; idx += 256)
        g_corr[(size_t)head * HD * HD + idx] = sc[idx >> 6][idx & 63];
}

// ---------------------------------------------------------------------------
// Meff: MeffT[b][o][h*64+d] = sum_e corr[b,h][d][e] * Wout[o][h*64+e]
// One block per head.
// ---------------------------------------------------------------------------
__global__ __launch_bounds__(256) void meff_kernel(const float* __restrict__ Wout) {
    const int head = blockIdx.x;
    const int b = head >> 4, h = head & 15;
    const int tid = threadIdx.x;
    __shared__ float sc[HD][HD + 1];

    for (int idx = tid; idx < HD * HD; idx += 256)
        sc[idx >> 6][idx & 63] = g_corr[(size_t)head * HD * HD + idx];
    __syncthreads();

    float* Mb = g_meffT + (size_t)b * D_MODEL * D_MODEL + h * HD;
    const float* Wb = Wout + h * HD;

    for (int idx = tid; idx < D_MODEL * HD; idx += 256) {
        int o = idx >> 6, d = idx & 63;
        const float* wrow = Wb + (size_t)o * D_MODEL;
        float s = 0.f;
        #pragma unroll
        for (int e = 0; e < HD; e++) s += sc[d][e] * wrow[e];
        Mb[(size_t)o * D_MODEL + d] = s;
    }
}

// ---------------------------------------------------------------------------
// Launch
// ---------------------------------------------------------------------------
extern "C" void kernel_launch(void* const* d_in, const int* in_sizes, int n_in,
                              void* d_out, int out_size) {
    const float* query = (const float*)d_in[0];
    const float* Wqkv  = (const float*)d_in[1];
    const float* bqkv  = (const float*)d_in[2];
    const float* Wout  = (const float*)d_in[3];
    const float* bout  = (const float*)d_in[4];
    float* out = (float*)d_out;

    void* p;
    cudaGetSymbolAddress(&p, g_qkv);
    float* qkv = (float*)p;
    cudaGetSymbolAddress(&p, g_meffT);
    float* meffT = (float*)p;

    // 1. zero stats accumulator
    {
        int total = NHEADS_TOTAL * STATS_PER_HEAD;
        zero_stats_kernel<<<(total + 1023) / 1024, 1024>>>();
    }

    // 2. qkv = query @ Wqkv^T + bqkv
    gemm_nt_kernel<<<dim3(QKV_LD / GBN, NROWS / GBM, 1), 256>>>(
        query, D_MODEL, 0,
        Wqkv, 0,
        bqkv,
        qkv, QKV_LD, 0,
        D_MODEL);

    // 3. per-head stats
    stats_kernel<<<dim3(TSPLIT, NHEADS_TOTAL), 256>>>(qkv);

    // 4. correlation + softmax
    corr_kernel<<<NHEADS_TOTAL, 256>>>();

    // 5. Meff_b = blockdiag(corr_b) @ Wout^T  (stored as MeffT[b][o][d])
    meff_kernel<<<NHEADS_TOTAL, 256>>>(Wout);

    // 6. out[t*4+z][o] = sum_d v[t*4+z][d] * MeffT[z][o][d] + bout[o]
    gemm_nt_kernel<<<dim3(D_MODEL / GBN, T_LEN / GBM, BATCH), 256>>>(
        qkv + 2 * D_MODEL, BATCH * QKV_LD, QKV_LD,
        meffT, (long)D_MODEL * D_MODEL,
        bout,
        out, BATCH * D_MODEL, D_MODEL,
        D_MODEL);
}

// round 3
// speedup vs baseline: 2.4903x; 2.4903x over previous
#include <cuda_runtime.h>
#include <cstdint>

// Problem constants
#define T_LEN   8192
#define BATCH   4
#define D_MODEL 1024
#define NHEAD   16
#define HD      64
#define QKV_LD  (3 * D_MODEL)        // 3072
#define NROWS   (T_LEN * BATCH)      // 32768
#define NHEADS_TOTAL (BATCH * NHEAD) // 64
#define STATS_PER_HEAD 4352

// Scratch (device globals: allocation-free)
__device__ float g_qkv[(size_t)NROWS * QKV_LD];                    // 384 MB
__device__ float g_meffT[(size_t)BATCH * D_MODEL * D_MODEL];       // 16 MB
__device__ float g_stats[NHEADS_TOTAL * STATS_PER_HEAD];
__device__ float g_corr[NHEADS_TOTAL * HD * HD];

// ===========================================================================
// helpers
// ===========================================================================
__device__ __forceinline__ uint32_t smem_to_u32(const void* p) {
    uint32_t a;
    asm("{ .reg .u64 t; cvta.to.shared.u64 t, %1; cvt.u32.u64 %0, t; }"
        : "=r"(a) : "l"(p));
    return a;
}

__device__ __forceinline__ void ldsm4(uint32_t (&r)[4], uint32_t addr) {
    asm volatile("ldmatrix.sync.aligned.m8n8.x4.shared.b16 {%0,%1,%2,%3}, [%4];"
        : "=r"(r[0]), "=r"(r[1]), "=r"(r[2]), "=r"(r[3]) : "r"(addr));
}

__device__ __forceinline__ void mma16816(float (&c)[4], const uint32_t (&a)[4],
                                         uint32_t b0, uint32_t b1) {
    asm volatile(
        "mma.sync.aligned.m16n8k16.row.col.f32.bf16.bf16.f32 "
        "{%0,%1,%2,%3}, {%4,%5,%6,%7}, {%8,%9}, {%0,%1,%2,%3};"
        : "+f"(c[0]), "+f"(c[1]), "+f"(c[2]), "+f"(c[3])
        : "r"(a[0]), "r"(a[1]), "r"(a[2]), "r"(a[3]), "r"(b0), "r"(b1));
}

// ===========================================================================
// bf16-split-3 HMMA GEMM (NT): C[m,n] = sum_k A[m,k]*B[n,k] + bias[n]
// 128x128x32 CTA tile, 8 warps (2x4), warp tile 64x32 via m16n8k16.
// smem rows padded to 80B (32 bf16 + 16B) for conflict-free ldmatrix.
// ===========================================================================
#define BM 128
#define BN 128
#define BK 32
#define ROWB 80                    // bytes per smem row
#define TILEB (128 * ROWB)         // 10240 per tile
#define OFF_AHI 0
#define OFF_ALO (1 * TILEB)
#define OFF_BHI (2 * TILEB)
#define OFF_BLO (3 * TILEB)
#define BUFB (4 * TILEB)           // 40960
#define SMEMB (2 * BUFB)           // 81920

__global__ void __launch_bounds__(256) gemm_mma_kernel(
    const float* __restrict__ A, int strideA, long long batchA,
    const float* __restrict__ B, long long batchB,
    const float* __restrict__ bias,
    float* __restrict__ C, int strideC, long long batchC,
    int K)
{
    extern __shared__ char smem[];
    const uint32_t sb = smem_to_u32(smem);
    const int tid = threadIdx.x;
    const int lane = tid & 31;
    const int wid = tid >> 5;
    const int wm = (wid >> 2) * 64;   // warp m offset (0 or 64)
    const int wn = (wid & 3) * 32;    // warp n offset
    const int z = blockIdx.z;

    const float* Ab = A + (size_t)blockIdx.y * BM * strideA + (size_t)z * batchA;
    const float* Bb = B + (size_t)blockIdx.x * BN * K + (size_t)z * batchB;

    // per-thread load slots: 4 A quads + 4 B quads
    // qi = i*256 + tid; row = qi>>3 (0..127), c4 = (qi&7)*4
    float4 pa[4], pb[4];

    float acc[4][4][4];
    #pragma unroll
    for (int mt = 0; mt < 4; mt++)
        #pragma unroll
        for (int nt = 0; nt < 4; nt++)
            #pragma unroll
            for (int r = 0; r < 4; r++) acc[mt][nt][r] = 0.0f;

    const int NKT = K / BK;

    // ---- load chunk kt into registers ----
    #define LOAD_CHUNK(kt) do { \
        const float* Akp = Ab + (kt) * BK; \
        const float* Bkp = Bb + (kt) * BK; \
        _Pragma("unroll") \
        for (int i = 0; i < 4; i++) { \
            const int qi = i * 256 + tid; \
            const int row = qi >> 3, c4 = (qi & 7) * 4; \
            pa[i] = *(const float4*)(Akp + (size_t)row * strideA + c4); \
            pb[i] = *(const float4*)(Bkp + (size_t)row * K + c4); \
        } \
    } while (0)

    // ---- convert + store regs into smem buffer b ----
    #define STORE_CHUNK(b) do { \
        char* bufp = smem + (b) * BUFB; \
        _Pragma("unroll") \
        for (int i = 0; i < 4; i++) { \
            const int qi = i * 256 + tid; \
            const int row = qi >> 3, c4 = (qi & 7) * 4; \
            const uint32_t off = row * ROWB + c4 * 2; \
            float4 v = pa[i]; \
            _Pragma("unroll") \
            for (int s = 0; s < 2; s++) { \
                const uint32_t x0 = __float_as_uint(v.x); \
                const uint32_t x1 = __float_as_uint(v.y); \
                const uint32_t x2 = __float_as_uint(v.z); \
                const uint32_t x3 = __float_as_uint(v.w); \
                const uint32_t h0 = __byte_perm(x0, x1, 0x7632); \
                const uint32_t h1 = __byte_perm(x2, x3, 0x7632); \
                const float r0 = v.x - __uint_as_float(x0 & 0xFFFF0000u); \
                const float r1 = v.y - __uint_as_float(x1 & 0xFFFF0000u); \
                const float r2 = v.z - __uint_as_float(x2 & 0xFFFF0000u); \
                const float r3 = v.w - __uint_as_float(x3 & 0xFFFF0000u); \
                const uint32_t l0 = __byte_perm(__float_as_uint(r0), __float_as_uint(r1), 0x7632); \
                const uint32_t l1 = __byte_perm(__float_as_uint(r2), __float_as_uint(r3), 0x7632); \
                if (s == 0) { \
                    *(uint2*)(bufp + OFF_AHI + off) = make_uint2(h0, h1); \
                    *(uint2*)(bufp + OFF_ALO + off) = make_uint2(l0, l1); \
                    v = pb[i]; \
                } else { \
                    *(uint2*)(bufp + OFF_BHI + off) = make_uint2(h0, h1); \
                    *(uint2*)(bufp + OFF_BLO + off) = make_uint2(l0, l1); \
                } \
            } \
        } \
    } while (0)

    LOAD_CHUNK(0);
    STORE_CHUNK(0);
    __syncthreads();

    // frag address components (constant per thread)
    const uint32_t a_off = (uint32_t)((lane & 15) * ROWB + (lane >> 4) * 16);
    const uint32_t b_row = (uint32_t)((lane & 7) + ((lane >> 4) << 3));
    const uint32_t b_off = (uint32_t)(b_row * ROWB + ((lane >> 3) & 1) * 16);

    for (int kt = 0; kt < NKT; kt++) {
        const bool pf = (kt + 1 < NKT);
        if (pf) LOAD_CHUNK(kt + 1);

        const uint32_t base = sb + (kt & 1) * BUFB;
        #pragma unroll
        for (int kk = 0; kk < 2; kk++) {
            uint32_t ahi[4][4], alo[4][4], bhi[2][4], blo[2][4];
            const uint32_t koff = kk * 32;
            #pragma unroll
            for (int mt = 0; mt < 4; mt++) {
                const uint32_t ra = base + (wm + mt * 16) * ROWB + a_off + koff;
                ldsm4(ahi[mt], ra + OFF_AHI);
                ldsm4(alo[mt], ra + OFF_ALO);
            }
            #pragma unroll
            for (int ng = 0; ng < 2; ng++) {
                const uint32_t rb = base + (wn + ng * 16) * ROWB + b_off + koff;
                ldsm4(bhi[ng], rb + OFF_BHI);
                ldsm4(blo[ng], rb + OFF_BLO);
            }
            #pragma unroll
            for (int mt = 0; mt < 4; mt++) {
                #pragma unroll
                for (int ng = 0; ng < 2; ng++) {
                    mma16816(acc[mt][2*ng],   ahi[mt], bhi[ng][0], bhi[ng][1]);
                    mma16816(acc[mt][2*ng+1], ahi[mt], bhi[ng][2], bhi[ng][3]);
                    mma16816(acc[mt][2*ng],   ahi[mt], blo[ng][0], blo[ng][1]);
                    mma16816(acc[mt][2*ng+1], ahi[mt], blo[ng][2], blo[ng][3]);
                    mma16816(acc[mt][2*ng],   alo[mt], bhi[ng][0], bhi[ng][1]);
                    mma16816(acc[mt][2*ng+1], alo[mt], bhi[ng][2], bhi[ng][3]);
                }
            }
        }

        if (pf) STORE_CHUNK((kt + 1) & 1);
        __syncthreads();
    }

    // ---- epilogue ----
    const int rbase = blockIdx.y * BM + wm + (lane >> 2);
    const int cbase = blockIdx.x * BN + wn + (lane & 3) * 2;
    float* Cz = C + (size_t)z * batchC;
    #pragma unroll
    for (int mt = 0; mt < 4; mt++) {
        #pragma unroll
        for (int nt = 0; nt < 4; nt++) {
            const int row = rbase + mt * 16;
            const int col = cbase + nt * 8;
            const float b0 = bias[col], b1 = bias[col + 1];
            float2 o0, o1;
            o0.x = acc[mt][nt][0] + b0; o0.y = acc[mt][nt][1] + b1;
            o1.x = acc[mt][nt][2] + b0; o1.y = acc[mt][nt][3] + b1;
            *(float2*)(Cz + (size_t)row * strideC + col) = o0;
            *(float2*)(Cz + (size_t)(row + 8) * strideC + col) = o1;
        }
    }
}

// ===========================================================================
// Zero the stats accumulator
// ===========================================================================
__global__ void zero_stats_kernel() {
    int idx = blockIdx.x * blockDim.x + threadIdx.x;
    if (idx < NHEADS_TOTAL * STATS_PER_HEAD) g_stats[idx] = 0.0f;
}

// ===========================================================================
// Stats: per head (b,h) accumulate C[i][j]=sum_t q_i k_j, Sq, Sk, Sqq, Skk
// ===========================================================================
#define TSPLIT 8
#define TCHUNK (T_LEN / TSPLIT)   // 1024

__global__ __launch_bounds__(256) void stats_kernel(const float* __restrict__ qkv) {
    const int head = blockIdx.y;
    const int b = head >> 4, h = head & 15;
    const int tid = threadIdx.x;

    __shared__ float qs[16][HD];
    __shared__ float ks[16][HD];

    const float* qbase = qkv + (size_t)b * QKV_LD + h * HD;
    const float* kbase = qbase + D_MODEL;

    float acc[4][4];
    #pragma unroll
    for (int i = 0; i < 4; i++)
        #pragma unroll
        for (int j = 0; j < 4; j++) acc[i][j] = 0.0f;
    float sq = 0.f, sqq = 0.f, sk = 0.f, skk = 0.f;

    const int i0 = (tid >> 4) * 4, j0 = (tid & 15) * 4;
    const int lrow = tid >> 4;
    const int lcol = (tid & 15) * 4;

    const int tstart = blockIdx.x * TCHUNK;
    for (int t0 = tstart; t0 < tstart + TCHUNK; t0 += 16) {
        size_t grow = (size_t)(t0 + lrow) * BATCH * QKV_LD;
        *(float4*)&qs[lrow][lcol] = *(const float4*)(qbase + grow + lcol);
        *(float4*)&ks[lrow][lcol] = *(const float4*)(kbase + grow + lcol);
        __syncthreads();

        if (tid < 64) {
            #pragma unroll
            for (int tt = 0; tt < 16; tt++) {
                float v = qs[tt][tid]; sq += v; sqq += v * v;
            }
        } else if (tid < 128) {
            int j = tid - 64;
            #pragma unroll
            for (int tt = 0; tt < 16; tt++) {
                float v = ks[tt][j]; sk += v; skk += v * v;
            }
        }
        #pragma unroll
        for (int tt = 0; tt < 16; tt++) {
            float4 qa = *(const float4*)&qs[tt][i0];
            float4 kb = *(const float4*)&ks[tt][j0];
            float qv[4] = {qa.x, qa.y, qa.z, qa.w};
            float kv[4] = {kb.x, kb.y, kb.z, kb.w};
            #pragma unroll
            for (int ii = 0; ii < 4; ii++)
                #pragma unroll
                for (int jj = 0; jj < 4; jj++)
                    acc[ii][jj] += qv[ii] * kv[jj];
        }
        __syncthreads();
    }

    float* st = g_stats + (size_t)head * STATS_PER_HEAD;
    #pragma unroll
    for (int ii = 0; ii < 4; ii++)
        #pragma unroll
        for (int jj = 0; jj < 4; jj++)
            atomicAdd(&st[(i0 + ii) * HD + (j0 + jj)], acc[ii][jj]);
    if (tid < 64) {
        atomicAdd(&st[4096 + tid], sq);
        atomicAdd(&st[4224 + tid], sqq);
    } else if (tid < 128) {
        atomicAdd(&st[4160 + (tid - 64)], sk);
        atomicAdd(&st[4288 + (tid - 64)], skk);
    }
}

// ===========================================================================
// Corr: corr = softmax_i(clip(cov/sqrt(sx*sy),0,1))
// ===========================================================================
__global__ __launch_bounds__(256) void corr_kernel() {
    const int head = blockIdx.x;
    const int tid = threadIdx.x;
    __shared__ float sc[HD][HD + 1];
    __shared__ float mq[HD], mk[HD], isx[HD], isy[HD];

    const float* st = g_stats + (size_t)head * STATS_PER_HEAD;
    const float invT = 1.0f / (float)T_LEN;

    if (tid < 64) {
        float s = st[4096 + tid], s2 = st[4224 + tid];
        mq[tid] = s;
        isx[tid] = rsqrtf(s2 - s * s * invT);
    } else if (tid < 128) {
        int j = tid - 64;
        float s = st[4160 + j], s2 = st[4288 + j];
        mk[j] = s;
        isy[j] = rsqrtf(s2 - s * s * invT);
    }
    __syncthreads();

    for (int idx = tid; idx < HD * HD; idx += 256) {
        int i = idx >> 6, j = idx & 63;
        float cov = st[idx] - mq[i] * mk[j] * invT;
        float c = cov * isx[i] * isy[j];
        c = fminf(fmaxf(c, 0.0f), 1.0f);
        sc[i][j] = c;
    }
    __syncthreads();

    if (tid < 64) {
        int j = tid;
        float mx = -1e30f;
        #pragma unroll 4
        for (int i = 0; i < HD; i++) mx = fmaxf(mx, sc[i][j]);
        float sum = 0.f;
        #pragma unroll 4
        for (int i = 0; i < HD; i++) {
            float e = expf(sc[i][j] - mx);
            sc[i][j] = e; sum += e;
        }
        float inv = 1.0f / sum;
        #pragma unroll 4
        for (int i = 0; i < HD; i++) sc[i][j] *= inv;
    }
    __syncthreads();

    for (int idx = tid; idx < HD * HD; idx += 256)
        g_corr[(size_t)head * HD * HD + idx] = sc[idx >> 6][idx & 63];
}

// ===========================================================================
// Meff: MeffT[b][o][h*64+d] = sum_e corr[b,h][d][e] * Wout[o][h*64+e]
// ===========================================================================
__global__ __launch_bounds__(256) void meff_kernel(const float* __restrict__ Wout) {
    const int head = blockIdx.x;
    const int b = head >> 4, h = head & 15;
    const int tid = threadIdx.x;
    __shared__ float sc[HD][HD + 1];

    for (int idx = tid; idx < HD * HD; idx += 256)
        sc[idx >> 6][idx & 63] = g_corr[(size_t)head * HD * HD + idx];
    __syncthreads();

    float* Mb = g_meffT + (size_t)b * D_MODEL * D_MODEL + h * HD;
    const float* Wb = Wout + h * HD;

    for (int idx = tid; idx < D_MODEL * HD; idx += 256) {
        int o = idx >> 6, d = idx & 63;
        const float* wrow = Wb + (size_t)o * D_MODEL;
        float s = 0.f;
        #pragma unroll
        for (int e = 0; e < HD; e++) s += sc[d][e] * wrow[e];
        Mb[(size_t)o * D_MODEL + d] = s;
    }
}

// ===========================================================================
// Launch
// ===========================================================================
extern "C" void kernel_launch(void* const* d_in, const int* in_sizes, int n_in,
                              void* d_out, int out_size) {
    const float* query = (const float*)d_in[0];
    const float* Wqkv  = (const float*)d_in[1];
    const float* bqkv  = (const float*)d_in[2];
    const float* Wout  = (const float*)d_in[3];
    const float* bout  = (const float*)d_in[4];
    float* out = (float*)d_out;

    void* p;
    cudaGetSymbolAddress(&p, g_qkv);
    float* qkv = (float*)p;
    cudaGetSymbolAddress(&p, g_meffT);
    float* meffT = (float*)p;

    cudaFuncSetAttribute(gemm_mma_kernel,
                         cudaFuncAttributeMaxDynamicSharedMemorySize, SMEMB);

    // 1. zero stats accumulator
    {
        int total = NHEADS_TOTAL * STATS_PER_HEAD;
        zero_stats_kernel<<<(total + 1023) / 1024, 1024>>>();
    }

    // 2. qkv = query @ Wqkv^T + bqkv   [32768 x 3072], K=1024
    gemm_mma_kernel<<<dim3(QKV_LD / BN, NROWS / BM, 1), 256, SMEMB>>>(
        query, D_MODEL, 0,
        Wqkv, 0,
        bqkv,
        qkv, QKV_LD, 0,
        D_MODEL);

    // 3. per-head stats
    stats_kernel<<<dim3(TSPLIT, NHEADS_TOTAL), 256>>>(qkv);

    // 4. correlation + softmax
    corr_kernel<<<NHEADS_TOTAL, 256>>>();

    // 5. Meff_b = blockdiag(corr_b) @ Wout^T
    meff_kernel<<<NHEADS_TOTAL, 256>>>(Wout);

    // 6. out[t][z][:] = v[t][z][:] @ MeffT[z]^T + bout   per batch z
    gemm_mma_kernel<<<dim3(D_MODEL / BN, T_LEN / BM, BATCH), 256, SMEMB>>>(
        qkv + 2 * D_MODEL, BATCH * QKV_LD, QKV_LD,
        meffT, (long long)D_MODEL * D_MODEL,
        bout,
        out, BATCH * D_MODEL, D_MODEL,
        D_MODEL);
}

// round 4
// speedup vs baseline: 3.0051x; 1.2067x over previous
#include <cuda_runtime.h>
#include <cuda_fp16.h>
#include <cstdint>

// Problem constants
#define T_LEN   8192
#define BATCH   4
#define D_MODEL 1024
#define NHEAD   16
#define HD      64
#define QKV_LD  (3 * D_MODEL)        // 3072
#define NROWS   (T_LEN * BATCH)      // 32768
#define NHEADS_TOTAL (BATCH * NHEAD) // 64
#define STATS_PER_HEAD 4352

// Scratch (device globals: allocation-free)
__device__ float  g_qkv[(size_t)NROWS * QKV_LD];                 // 384 MB (q,k used)
__device__ __half g_qh[(size_t)NROWS * D_MODEL];                 // 64 MB  query fp16
__device__ __half g_wh[(size_t)QKV_LD * D_MODEL];                // 6 MB   Wqkv hi
__device__ __half g_wl[(size_t)QKV_LD * D_MODEL];                // 6 MB   Wqkv lo
__device__ __half g_vh[(size_t)NROWS * D_MODEL];                 // 64 MB  v fp16
__device__ __half g_vl[(size_t)NROWS * D_MODEL];                 // (lo unused for A, kept for layout symmetry)
__device__ __half g_mh[(size_t)BATCH * D_MODEL * D_MODEL];       // 8 MB  Meff hi
__device__ __half g_ml[(size_t)BATCH * D_MODEL * D_MODEL];       // 8 MB  Meff lo
__device__ float  g_stats[NHEADS_TOTAL * STATS_PER_HEAD];
__device__ float  g_corr[NHEADS_TOTAL * HD * HD];

// ===========================================================================
// helpers
// ===========================================================================
__device__ __forceinline__ uint32_t smem_to_u32(const void* p) {
    uint32_t a;
    asm("{ .reg .u64 t; cvta.to.shared.u64 t, %1; cvt.u32.u64 %0, t; }"
        : "=r"(a) : "l"(p));
    return a;
}

__device__ __forceinline__ void ldsm4(uint32_t (&r)[4], uint32_t addr) {
    asm volatile("ldmatrix.sync.aligned.m8n8.x4.shared.b16 {%0,%1,%2,%3}, [%4];"
        : "=r"(r[0]), "=r"(r[1]), "=r"(r[2]), "=r"(r[3]) : "r"(addr));
}

__device__ __forceinline__ void mma16816(float (&c)[4], const uint32_t (&a)[4],
                                         uint32_t b0, uint32_t b1) {
    asm volatile(
        "mma.sync.aligned.m16n8k16.row.col.f32.f16.f16.f32 "
        "{%0,%1,%2,%3}, {%4,%5,%6,%7}, {%8,%9}, {%0,%1,%2,%3};"
        : "+f"(c[0]), "+f"(c[1]), "+f"(c[2]), "+f"(c[3])
        : "r"(a[0]), "r"(a[1]), "r"(a[2]), "r"(a[3]), "r"(b0), "r"(b1));
}

#define CP_COMMIT() asm volatile("cp.async.commit_group;" ::: "memory")
#define CP16(dst, src) \
    asm volatile("cp.async.cg.shared.global [%0], [%1], 16;" \
        :: "r"(dst), "l"(src) : "memory")

// ===========================================================================
// fp16 2-pass HMMA GEMM (NT): C[m,n] = sum_k A[m,k]*(Bhi+Blo)[n,k] + bias[n]
// A plain fp16, B split hi/lo. 128x128x32 CTA tile, 8 warps (2x4),
// 3-stage cp.async pipeline. smem rows padded to 80B, conflict-free ldmatrix.
// Optional epilogue: columns >= 2048 written as fp16 hi/lo split (v output).
// ===========================================================================
#define BM 128
#define BN 128
#define BK 32
#define ROWB 80
#define TILEB (128 * ROWB)      // 10240
#define OFF_A  0
#define OFF_BH TILEB
#define OFF_BL (2 * TILEB)
#define STAGEB (3 * TILEB)      // 30720
#define NSTAGE 3
#define SMEMB (NSTAGE * STAGEB) // 92160

__global__ void __launch_bounds__(256, 2) gemm_fp16_kernel(
    const __half* __restrict__ Ah, int strideA, long long batchA,
    const __half* __restrict__ Bh, const __half* __restrict__ Bl,
    int strideB, long long batchB,
    const float* __restrict__ bias,
    float* __restrict__ C, int strideC, long long batchC,
    __half* __restrict__ Vh, __half* __restrict__ Vl,
    int K)
{
    extern __shared__ char smem[];
    const uint32_t sb = smem_to_u32(smem);
    const int tid = threadIdx.x;
    const int lane = tid & 31;
    const int wid = tid >> 5;
    const int wm = (wid >> 2) * 64;
    const int wn = (wid & 3) * 32;
    const int z = blockIdx.z;

    const __half* Ab  = Ah + (size_t)blockIdx.y * BM * strideA + (size_t)z * batchA;
    const __half* Bhb = Bh + (size_t)blockIdx.x * BN * strideB + (size_t)z * batchB;
    const __half* Blb = Bl + (size_t)blockIdx.x * BN * strideB + (size_t)z * batchB;

    // loader slots: 6 x 16B per thread per stage.
    // i=0,1 -> A (512 chunks); i=2,3 -> Bhi; i=4,5 -> Blo.
    const int lrow = ((tid & 127) | (((tid >> 7) & 1) << 7)) ;  // placeholder; computed per-slot below

    float acc[4][4][4];
    #pragma unroll
    for (int mt = 0; mt < 4; mt++)
        #pragma unroll
        for (int nt = 0; nt < 4; nt++)
            #pragma unroll
            for (int r = 0; r < 4; r++) acc[mt][nt][r] = 0.0f;

    const int NKT = K / BK;

    #define ISSUE_STAGE(kt, buf) do { \
        const uint32_t sbase = sb + (buf) * STAGEB; \
        _Pragma("unroll") \
        for (int i = 0; i < 6; i++) { \
            const int ci = i * 256 + tid; \
            const int r_ = (ci & 511) >> 2, c_ = ci & 3; \
            const __half* src; uint32_t dst; \
            if (i < 2) { \
                src = Ab + (size_t)r_ * strideA + (kt) * BK + c_ * 8; \
                dst = sbase + OFF_A + r_ * ROWB + c_ * 16; \
            } else if (i < 4) { \
                src = Bhb + (size_t)r_ * strideB + (kt) * BK + c_ * 8; \
                dst = sbase + OFF_BH + r_ * ROWB + c_ * 16; \
            } else { \
                src = Blb + (size_t)r_ * strideB + (kt) * BK + c_ * 8; \
                dst = sbase + OFF_BL + r_ * ROWB + c_ * 16; \
            } \
            CP16(dst, src); \
        } \
    } while (0)

    ISSUE_STAGE(0, 0); CP_COMMIT();
    ISSUE_STAGE(1, 1); CP_COMMIT();

    // frag address components (constant per thread)
    const uint32_t a_off = (uint32_t)((lane & 15) * ROWB + (lane >> 4) * 16);
    const uint32_t b_row = (uint32_t)((lane & 7) + ((lane >> 4) << 3));
    const uint32_t b_off = (uint32_t)(b_row * ROWB + ((lane >> 3) & 1) * 16);

    for (int kt = 0; kt < NKT; kt++) {
        asm volatile("cp.async.wait_group 1;" ::: "memory");
        __syncthreads();

        if (kt + 2 < NKT) ISSUE_STAGE(kt + 2, (kt + 2) % NSTAGE);
        CP_COMMIT();

        const uint32_t base = sb + (kt % NSTAGE) * STAGEB;
        #pragma unroll
        for (int kk = 0; kk < 2; kk++) {
            uint32_t a[4][4], bh[2][4], bl[2][4];
            const uint32_t koff = kk * 32;
            #pragma unroll
            for (int mt = 0; mt < 4; mt++)
                ldsm4(a[mt], base + OFF_A + (wm + mt * 16) * ROWB + a_off + koff);
            #pragma unroll
            for (int ng = 0; ng < 2; ng++) {
                ldsm4(bh[ng], base + OFF_BH + (wn + ng * 16) * ROWB + b_off + koff);
                ldsm4(bl[ng], base + OFF_BL + (wn + ng * 16) * ROWB + b_off + koff);
            }
            #pragma unroll
            for (int mt = 0; mt < 4; mt++) {
                #pragma unroll
                for (int ng = 0; ng < 2; ng++) {
                    mma16816(acc[mt][2*ng],   a[mt], bh[ng][0], bh[ng][1]);
                    mma16816(acc[mt][2*ng+1], a[mt], bh[ng][2], bh[ng][3]);
                    mma16816(acc[mt][2*ng],   a[mt], bl[ng][0], bl[ng][1]);
                    mma16816(acc[mt][2*ng+1], a[mt], bl[ng][2], bl[ng][3]);
                }
            }
        }
    }

    // ---- epilogue ----
    const int rbase = blockIdx.y * BM + wm + (lane >> 2);
    const int cbase = blockIdx.x * BN + wn + (lane & 3) * 2;
    float* Cz = C + (size_t)z * batchC;
    #pragma unroll
    for (int mt = 0; mt < 4; mt++) {
        #pragma unroll
        for (int nt = 0; nt < 4; nt++) {
            const int row = rbase + mt * 16;
            const int col = cbase + nt * 8;
            const float b0 = bias[col], b1 = bias[col + 1];
            const float v0 = acc[mt][nt][0] + b0, v1 = acc[mt][nt][1] + b1;
            const float v2 = acc[mt][nt][2] + b0, v3 = acc[mt][nt][3] + b1;
            if (Vh != nullptr && col >= 2048) {
                const int vc = col - 2048;
                __half h0 = __float2half_rn(v0), h1 = __float2half_rn(v1);
                __half h2 = __float2half_rn(v2), h3 = __float2half_rn(v3);
                __half l0 = __float2half_rn(v0 - __half2float(h0));
                __half l1 = __float2half_rn(v1 - __half2float(h1));
                __half l2 = __float2half_rn(v2 - __half2float(h2));
                __half l3 = __float2half_rn(v3 - __half2float(h3));
                *(__half2*)(Vh + (size_t)row * D_MODEL + vc)       = __halves2half2(h0, h1);
                *(__half2*)(Vh + (size_t)(row + 8) * D_MODEL + vc) = __halves2half2(h2, h3);
                *(__half2*)(Vl + (size_t)row * D_MODEL + vc)       = __halves2half2(l0, l1);
                *(__half2*)(Vl + (size_t)(row + 8) * D_MODEL + vc) = __halves2half2(l2, l3);
            } else {
                float2 o0, o1;
                o0.x = v0; o0.y = v1; o1.x = v2; o1.y = v3;
                *(float2*)(Cz + (size_t)row * strideC + col) = o0;
                *(float2*)(Cz + (size_t)(row + 8) * strideC + col) = o1;
            }
        }
    }
}

// ===========================================================================
// Converters
// ===========================================================================
__global__ void conv_half_kernel(const float* __restrict__ in,
                                 __half* __restrict__ outh, int n4) {
    int idx = blockIdx.x * blockDim.x + threadIdx.x;
    if (idx < n4) {
        float4 v = ((const float4*)in)[idx];
        ((__half2*)outh)[2 * idx]     = __floats2half2_rn(v.x, v.y);
        ((__half2*)outh)[2 * idx + 1] = __floats2half2_rn(v.z, v.w);
    }
}

__global__ void conv_split_kernel(const float* __restrict__ in,
                                  __half* __restrict__ outh,
                                  __half* __restrict__ outl, int n4) {
    int idx = blockIdx.x * blockDim.x + threadIdx.x;
    if (idx < n4) {
        float4 v = ((const float4*)in)[idx];
        __half h0 = __float2half_rn(v.x), h1 = __float2half_rn(v.y);
        __half h2 = __float2half_rn(v.z), h3 = __float2half_rn(v.w);
        ((__half2*)outh)[2 * idx]     = __halves2half2(h0, h1);
        ((__half2*)outh)[2 * idx + 1] = __halves2half2(h2, h3);
        __half l0 = __float2half_rn(v.x - __half2float(h0));
        __half l1 = __float2half_rn(v.y - __half2float(h1));
        __half l2 = __float2half_rn(v.z - __half2float(h2));
        __half l3 = __float2half_rn(v.w - __half2float(h3));
        ((__half2*)outl)[2 * idx]     = __halves2half2(l0, l1);
        ((__half2*)outl)[2 * idx + 1] = __halves2half2(l2, l3);
    }
}

// ===========================================================================
// Zero the stats accumulator
// ===========================================================================
__global__ void zero_stats_kernel() {
    int idx = blockIdx.x * blockDim.x + threadIdx.x;
    if (idx < NHEADS_TOTAL * STATS_PER_HEAD) g_stats[idx] = 0.0f;
}

// ===========================================================================
// Stats: per head (b,h) accumulate C[i][j]=sum_t q_i k_j, Sq, Sk, Sqq, Skk
// ===========================================================================
#define TSPLIT 8
#define TCHUNK (T_LEN / TSPLIT)   // 1024

__global__ __launch_bounds__(256) void stats_kernel(const float* __restrict__ qkv) {
    const int head = blockIdx.y;
    const int b = head >> 4, h = head & 15;
    const int tid = threadIdx.x;

    __shared__ float qs[16][HD];
    __shared__ float ks[16][HD];

    const float* qbase = qkv + (size_t)b * QKV_LD + h * HD;
    const float* kbase = qbase + D_MODEL;

    float acc[4][4];
    #pragma unroll
    for (int i = 0; i < 4; i++)
        #pragma unroll
        for (int j = 0; j < 4; j++) acc[i][j] = 0.0f;
    float sq = 0.f, sqq = 0.f, sk = 0.f, skk = 0.f;

    const int i0 = (tid >> 4) * 4, j0 = (tid & 15) * 4;
    const int lrow = tid >> 4;
    const int lcol = (tid & 15) * 4;

    const int tstart = blockIdx.x * TCHUNK;
    for (int t0 = tstart; t0 < tstart + TCHUNK; t0 += 16) {
        size_t grow = (size_t)(t0 + lrow) * BATCH * QKV_LD;
        *(float4*)&qs[lrow][lcol] = *(const float4*)(qbase + grow + lcol);
        *(float4*)&ks[lrow][lcol] = *(const float4*)(kbase + grow + lcol);
        __syncthreads();

        if (tid < 64) {
            #pragma unroll
            for (int tt = 0; tt < 16; tt++) {
                float v = qs[tt][tid]; sq += v; sqq += v * v;
            }
        } else if (tid < 128) {
            int j = tid - 64;
            #pragma unroll
            for (int tt = 0; tt < 16; tt++) {
                float v = ks[tt][j]; sk += v; skk += v * v;
            }
        }
        #pragma unroll
        for (int tt = 0; tt < 16; tt++) {
            float4 qa = *(const float4*)&qs[tt][i0];
            float4 kb = *(const float4*)&ks[tt][j0];
            float qv[4] = {qa.x, qa.y, qa.z, qa.w};
            float kv[4] = {kb.x, kb.y, kb.z, kb.w};
            #pragma unroll
            for (int ii = 0; ii < 4; ii++)
                #pragma unroll
                for (int jj = 0; jj < 4; jj++)
                    acc[ii][jj] += qv[ii] * kv[jj];
        }
        __syncthreads();
    }

    float* st = g_stats + (size_t)head * STATS_PER_HEAD;
    #pragma unroll
    for (int ii = 0; ii < 4; ii++)
        #pragma unroll
        for (int jj = 0; jj < 4; jj++)
            atomicAdd(&st[(i0 + ii) * HD + (j0 + jj)], acc[ii][jj]);
    if (tid < 64) {
        atomicAdd(&st[4096 + tid], sq);
        atomicAdd(&st[4224 + tid], sqq);
    } else if (tid < 128) {
        atomicAdd(&st[4160 + (tid - 64)], sk);
        atomicAdd(&st[4288 + (tid - 64)], skk);
    }
}

// ===========================================================================
// Corr: corr = softmax_i(clip(cov/sqrt(sx*sy),0,1))
// ===========================================================================
__global__ __launch_bounds__(256) void corr_kernel() {
    const int head = blockIdx.x;
    const int tid = threadIdx.x;
    __shared__ float sc[HD][HD + 1];
    __shared__ float mq[HD], mk[HD], isx[HD], isy[HD];

    const float* st = g_stats + (size_t)head * STATS_PER_HEAD;
    const float invT = 1.0f / (float)T_LEN;

    if (tid < 64) {
        float s = st[4096 + tid], s2 = st[4224 + tid];
        mq[tid] = s;
        isx[tid] = rsqrtf(s2 - s * s * invT);
    } else if (tid < 128) {
        int j = tid - 64;
        float s = st[4160 + j], s2 = st[4288 + j];
        mk[j] = s;
        isy[j] = rsqrtf(s2 - s * s * invT);
    }
    __syncthreads();

    for (int idx = tid; idx < HD * HD; idx += 256) {
        int i = idx >> 6, j = idx & 63;
        float cov = st[idx] - mq[i] * mk[j] * invT;
        float c = cov * isx[i] * isy[j];
        c = fminf(fmaxf(c, 0.0f), 1.0f);
        sc[i][j] = c;
    }
    __syncthreads();

    if (tid < 64) {
        int j = tid;
        float mx = -1e30f;
        #pragma unroll 4
        for (int i = 0; i < HD; i++) mx = fmaxf(mx, sc[i][j]);
        float sum = 0.f;
        #pragma unroll 4
        for (int i = 0; i < HD; i++) {
            float e = expf(sc[i][j] - mx);
            sc[i][j] = e; sum += e;
        }
        float inv = 1.0f / sum;
        #pragma unroll 4
        for (int i = 0; i < HD; i++) sc[i][j] *= inv;
    }
    __syncthreads();

    for (int idx = tid; idx < HD * HD; idx += 256)
        g_corr[(size_t)head * HD * HD + idx] = sc[idx >> 6][idx & 63];
}

// ===========================================================================
// Meff: Meff^T[b][o][h*64+d] = sum_e corr[b,h][d][e] * Wout[o][h*64+e]
// Emitted directly as fp16 hi/lo split for GEMM2's B operand.
// ===========================================================================
__global__ __launch_bounds__(256) void meff_kernel(const float* __restrict__ Wout) {
    const int head = blockIdx.x;
    const int b = head >> 4, h = head & 15;
    const int tid = threadIdx.x;
    __shared__ float sc[HD][HD + 1];

    for (int idx = tid; idx < HD * HD; idx += 256)
        sc[idx >> 6][idx & 63] = g_corr[(size_t)head * HD * HD + idx];
    __syncthreads();

    const size_t mbase = (size_t)b * D_MODEL * D_MODEL + h * HD;
    const float* Wb = Wout + h * HD;

    for (int idx = tid; idx < D_MODEL * HD; idx += 256) {
        int o = idx >> 6, d = idx & 63;
        const float* wrow = Wb + (size_t)o * D_MODEL;
        float s = 0.f;
        #pragma unroll
        for (int e = 0; e < HD; e++) s += sc[d][e] * wrow[e];
        __half hh = __float2half_rn(s);
        __half hl = __float2half_rn(s - __half2float(hh));
        g_mh[mbase + (size_t)o * D_MODEL + d] = hh;
        g_ml[mbase + (size_t)o * D_MODEL + d] = hl;
    }
}

// ===========================================================================
// Launch
// ===========================================================================
extern "C" void kernel_launch(void* const* d_in, const int* in_sizes, int n_in,
                              void* d_out, int out_size) {
    const float* query = (const float*)d_in[0];
    const float* Wqkv  = (const float*)d_in[1];
    const float* bqkv  = (const float*)d_in[2];
    const float* Wout  = (const float*)d_in[3];
    const float* bout  = (const float*)d_in[4];
    float* out = (float*)d_out;

    void* p;
    cudaGetSymbolAddress(&p, g_qkv);  float*  qkv = (float*)p;
    cudaGetSymbolAddress(&p, g_qh);   __half* qh  = (__half*)p;
    cudaGetSymbolAddress(&p, g_wh);   __half* wh  = (__half*)p;
    cudaGetSymbolAddress(&p, g_wl);   __half* wl  = (__half*)p;
    cudaGetSymbolAddress(&p, g_vh);   __half* vh  = (__half*)p;
    cudaGetSymbolAddress(&p, g_vl);   __half* vl  = (__half*)p;
    cudaGetSymbolAddress(&p, g_mh);   __half* mh  = (__half*)p;
    cudaGetSymbolAddress(&p, g_ml);   __half* ml  = (__half*)p;

    cudaFuncSetAttribute(gemm_fp16_kernel,
                         cudaFuncAttributeMaxDynamicSharedMemorySize, SMEMB);

    // 0. zero stats accumulator
    {
        int total = NHEADS_TOTAL * STATS_PER_HEAD;
        zero_stats_kernel<<<(total + 1023) / 1024, 1024>>>();
    }

    // 1. converters: query -> fp16, Wqkv -> fp16 hi/lo
    {
        int n4q = NROWS * D_MODEL / 4;      // 8388608
        conv_half_kernel<<<n4q / 256, 256>>>(query, qh, n4q);
        int n4w = QKV_LD * D_MODEL / 4;     // 786432
        conv_split_kernel<<<n4w / 256, 256>>>(Wqkv, wh, wl, n4w);
    }

    // 2. GEMM1: qkv = query @ Wqkv^T + bqkv. q,k -> fp32 g_qkv; v -> fp16 split.
    gemm_fp16_kernel<<<dim3(QKV_LD / BN, NROWS / BM, 1), 256, SMEMB>>>(
        qh, D_MODEL, 0,
        wh, wl, D_MODEL, 0,
        bqkv,
        qkv, QKV_LD, 0,
        vh, vl,
        D_MODEL);

    // 3. per-head stats
    stats_kernel<<<dim3(TSPLIT, NHEADS_TOTAL), 256>>>(qkv);

    // 4. correlation + softmax
    corr_kernel<<<NHEADS_TOTAL, 256>>>();

    // 5. Meff_b = blockdiag(corr_b) @ Wout^T  (fp16 hi/lo)
    meff_kernel<<<NHEADS_TOTAL, 256>>>(Wout);

    // 6. out = v @ Meff_b^T + bout   per batch z
    gemm_fp16_kernel<<<dim3(D_MODEL / BN, T_LEN / BM, BATCH), 256, SMEMB>>>(
        vh, BATCH * D_MODEL, D_MODEL,
        mh, ml, D_MODEL, (long long)D_MODEL * D_MODEL,
        bout,
        out, BATCH * D_MODEL, D_MODEL,
        nullptr, nullptr,
        D_MODEL);
}

// round 5
// speedup vs baseline: 3.0261x; 1.0070x over previous
#include <cuda_runtime.h>
#include <cuda_fp16.h>
#include <cstdint>

// Problem constants
#define T_LEN   8192
#define BATCH   4
#define D_MODEL 1024
#define NHEAD   16
#define HD      64
#define QKV_LD  (3 * D_MODEL)        // 3072
#define NROWS   (T_LEN * BATCH)      // 32768
#define NHEADS_TOTAL (BATCH * NHEAD) // 64
#define STATS_PER_HEAD 4352

// Scratch (device globals: allocation-free)
__device__ float  g_qkv[(size_t)NROWS * QKV_LD];                 // 384 MB (q,k used)
__device__ __half g_qh[(size_t)NROWS * D_MODEL];                 // 64 MB  query fp16
__device__ __half g_wh[(size_t)QKV_LD * D_MODEL];                // 6 MB   Wqkv hi
__device__ __half g_wl[(size_t)QKV_LD * D_MODEL];                // 6 MB   Wqkv lo
__device__ __half g_vh[(size_t)NROWS * D_MODEL];                 // 64 MB  v fp16 hi
__device__ __half g_vl[(size_t)NROWS * D_MODEL];                 // 64 MB  v fp16 lo
__device__ __half g_mh[(size_t)BATCH * D_MODEL * D_MODEL];       // 8 MB  Meff hi
__device__ __half g_ml[(size_t)BATCH * D_MODEL * D_MODEL];       // 8 MB  Meff lo
__device__ float  g_stats[NHEADS_TOTAL * STATS_PER_HEAD];
__device__ float  g_corr[NHEADS_TOTAL * HD * HD];

// ===========================================================================
// helpers
// ===========================================================================
__device__ __forceinline__ uint32_t smem_to_u32(const void* p) {
    uint32_t a;
    asm("{ .reg .u64 t; cvta.to.shared.u64 t, %1; cvt.u32.u64 %0, t; }"
        : "=r"(a) : "l"(p));
    return a;
}

__device__ __forceinline__ void ldsm4(uint32_t (&r)[4], uint32_t addr) {
    asm volatile("ldmatrix.sync.aligned.m8n8.x4.shared.b16 {%0,%1,%2,%3}, [%4];"
        : "=r"(r[0]), "=r"(r[1]), "=r"(r[2]), "=r"(r[3]) : "r"(addr));
}

__device__ __forceinline__ void mma16816(float (&c)[4], const uint32_t (&a)[4],
                                         uint32_t b0, uint32_t b1) {
    asm volatile(
        "mma.sync.aligned.m16n8k16.row.col.f32.f16.f16.f32 "
        "{%0,%1,%2,%3}, {%4,%5,%6,%7}, {%8,%9}, {%0,%1,%2,%3};"
        : "+f"(c[0]), "+f"(c[1]), "+f"(c[2]), "+f"(c[3])
        : "r"(a[0]), "r"(a[1]), "r"(a[2]), "r"(a[3]), "r"(b0), "r"(b1));
}

#define CP_COMMIT() asm volatile("cp.async.commit_group;" ::: "memory")
#define CP16(dst, src) \
    asm volatile("cp.async.cg.shared.global [%0], [%1], 16;" \
        :: "r"(dst), "l"(src) : "memory")

// ===========================================================================
// fp16 2-pass HMMA GEMM (NT): C[m,n] = sum_k A[m,k]*(Bhi+Blo)[n,k] + bias[n]
// A plain fp16, B split hi/lo. 256x128x32 CTA tile, 8 warps (4x2),
// warp tile 64x64. 4-stage cp.async pipeline. smem rows 80B (conflict-free).
// Optional epilogue: columns >= 2048 written as fp16 hi/lo split (v output).
// ===========================================================================
#define BM 256
#define BN 128
#define BK 32
#define ROWB 80
#define A_TILEB (256 * ROWB)    // 20480
#define B_TILEB (128 * ROWB)    // 10240
#define OFF_A  0
#define OFF_BH A_TILEB
#define OFF_BL (A_TILEB + B_TILEB)
#define STAGEB (A_TILEB + 2 * B_TILEB)  // 40960
#define NSTAGE 4
#define SMEMB (NSTAGE * STAGEB)         // 163840

__global__ void __launch_bounds__(256, 1) gemm_fp16_kernel(
    const __half* __restrict__ Ah, int strideA, long long batchA,
    const __half* __restrict__ Bh, const __half* __restrict__ Bl,
    int strideB, long long batchB,
    const float* __restrict__ bias,
    float* __restrict__ C, int strideC, long long batchC,
    __half* __restrict__ Vh, __half* __restrict__ Vl,
    int K)
{
    extern __shared__ char smem[];
    const uint32_t sb = smem_to_u32(smem);
    const int tid = threadIdx.x;
    const int lane = tid & 31;
    const int wid = tid >> 5;
    const int wm = (wid >> 1) * 64;   // 0,64,128,192
    const int wn = (wid & 1) * 64;    // 0,64
    const int z = blockIdx.z;

    const __half* Ab  = Ah + (size_t)blockIdx.y * BM * strideA + (size_t)z * batchA;
    const __half* Bhb = Bh + (size_t)blockIdx.x * BN * strideB + (size_t)z * batchB;
    const __half* Blb = Bl + (size_t)blockIdx.x * BN * strideB + (size_t)z * batchB;

    float acc[4][8][4];
    #pragma unroll
    for (int mt = 0; mt < 4; mt++)
        #pragma unroll
        for (int nt = 0; nt < 8; nt++)
            #pragma unroll
            for (int r = 0; r < 4; r++) acc[mt][nt][r] = 0.0f;

    const int NKT = K / BK;

    // 8 x 16B cp.async per thread per stage:
    // i<4 -> A (1024 chunks: 256 rows x 4), i=4,5 -> Bhi (512), i=6,7 -> Blo
    #define ISSUE_STAGE(kt, buf) do { \
        const uint32_t sbase = sb + (buf) * STAGEB; \
        _Pragma("unroll") \
        for (int i = 0; i < 8; i++) { \
            const int ci = i * 256 + tid; \
            const __half* src; uint32_t dst; \
            if (i < 4) { \
                const int r_ = ci >> 2, c_ = ci & 3; \
                src = Ab + (size_t)r_ * strideA + (kt) * BK + c_ * 8; \
                dst = sbase + OFF_A + r_ * ROWB + c_ * 16; \
            } else if (i < 6) { \
                const int j_ = ci - 1024, r_ = j_ >> 2, c_ = j_ & 3; \
                src = Bhb + (size_t)r_ * strideB + (kt) * BK + c_ * 8; \
                dst = sbase + OFF_BH + r_ * ROWB + c_ * 16; \
            } else { \
                const int j_ = ci - 1536, r_ = j_ >> 2, c_ = j_ & 3; \
                src = Blb + (size_t)r_ * strideB + (kt) * BK + c_ * 8; \
                dst = sbase + OFF_BL + r_ * ROWB + c_ * 16; \
            } \
            CP16(dst, src); \
        } \
    } while (0)

    ISSUE_STAGE(0, 0); CP_COMMIT();
    ISSUE_STAGE(1, 1); CP_COMMIT();
    ISSUE_STAGE(2, 2); CP_COMMIT();

    // frag address components (constant per thread)
    const uint32_t a_off = (uint32_t)((lane & 15) * ROWB + (lane >> 4) * 16);
    const uint32_t b_row = (uint32_t)((lane & 7) + ((lane >> 4) << 3));
    const uint32_t b_off = (uint32_t)(b_row * ROWB + ((lane >> 3) & 1) * 16);

    for (int kt = 0; kt < NKT; kt++) {
        asm volatile("cp.async.wait_group 2;" ::: "memory");
        __syncthreads();

        if (kt + 3 < NKT) { ISSUE_STAGE(kt + 3, (kt + 3) % NSTAGE); CP_COMMIT(); }

        const uint32_t base = sb + (kt % NSTAGE) * STAGEB;
        #pragma unroll
        for (int kk = 0; kk < 2; kk++) {
            const uint32_t koff = kk * 32;
            uint32_t a[4][4];
            #pragma unroll
            for (int mt = 0; mt < 4; mt++)
                ldsm4(a[mt], base + OFF_A + (wm + mt * 16) * ROWB + a_off + koff);
            #pragma unroll
            for (int ng = 0; ng < 4; ng++) {
                uint32_t bh[4], bl[4];
                const uint32_t rb = base + (wn + ng * 16) * ROWB + b_off + koff;
                ldsm4(bh, rb + OFF_BH);
                ldsm4(bl, rb + OFF_BL);
                #pragma unroll
                for (int mt = 0; mt < 4; mt++) {
                    mma16816(acc[mt][2*ng],   a[mt], bh[0], bh[1]);
                    mma16816(acc[mt][2*ng+1], a[mt], bh[2], bh[3]);
                    mma16816(acc[mt][2*ng],   a[mt], bl[0], bl[1]);
                    mma16816(acc[mt][2*ng+1], a[mt], bl[2], bl[3]);
                }
            }
        }
    }

    // ---- epilogue ----
    const int rbase = blockIdx.y * BM + wm + (lane >> 2);
    const int cbase = blockIdx.x * BN + wn + (lane & 3) * 2;
    float* Cz = C + (size_t)z * batchC;
    #pragma unroll
    for (int mt = 0; mt < 4; mt++) {
        #pragma unroll
        for (int nt = 0; nt < 8; nt++) {
            const int row = rbase + mt * 16;
            const int col = cbase + nt * 8;
            const float b0 = bias[col], b1 = bias[col + 1];
            const float v0 = acc[mt][nt][0] + b0, v1 = acc[mt][nt][1] + b1;
            const float v2 = acc[mt][nt][2] + b0, v3 = acc[mt][nt][3] + b1;
            if (Vh != nullptr && col >= 2048) {
                const int vc = col - 2048;
                __half h0 = __float2half_rn(v0), h1 = __float2half_rn(v1);
                __half h2 = __float2half_rn(v2), h3 = __float2half_rn(v3);
                __half l0 = __float2half_rn(v0 - __half2float(h0));
                __half l1 = __float2half_rn(v1 - __half2float(h1));
                __half l2 = __float2half_rn(v2 - __half2float(h2));
                __half l3 = __float2half_rn(v3 - __half2float(h3));
                *(__half2*)(Vh + (size_t)row * D_MODEL + vc)       = __halves2half2(h0, h1);
                *(__half2*)(Vh + (size_t)(row + 8) * D_MODEL + vc) = __halves2half2(h2, h3);
                *(__half2*)(Vl + (size_t)row * D_MODEL + vc)       = __halves2half2(l0, l1);
                *(__half2*)(Vl + (size_t)(row + 8) * D_MODEL + vc) = __halves2half2(l2, l3);
            } else {
                float2 o0, o1;
                o0.x = v0; o0.y = v1; o1.x = v2; o1.y = v3;
                *(float2*)(Cz + (size_t)row * strideC + col) = o0;
                *(float2*)(Cz + (size_t)(row + 8) * strideC + col) = o1;
            }
        }
    }
}

// ===========================================================================
// Converters
// ===========================================================================
__global__ void conv_half_kernel(const float* __restrict__ in,
                                 __half* __restrict__ outh, int n4) {
    int idx = blockIdx.x * blockDim.x + threadIdx.x;
    if (idx < n4) {
        float4 v = ((const float4*)in)[idx];
        ((__half2*)outh)[2 * idx]     = __floats2half2_rn(v.x, v.y);
        ((__half2*)outh)[2 * idx + 1] = __floats2half2_rn(v.z, v.w);
    }
}

__global__ void conv_split_kernel(const float* __restrict__ in,
                                  __half* __restrict__ outh,
                                  __half* __restrict__ outl, int n4) {
    int idx = blockIdx.x * blockDim.x + threadIdx.x;
    if (idx < n4) {
        float4 v = ((const float4*)in)[idx];
        __half h0 = __float2half_rn(v.x), h1 = __float2half_rn(v.y);
        __half h2 = __float2half_rn(v.z), h3 = __float2half_rn(v.w);
        ((__half2*)outh)[2 * idx]     = __halves2half2(h0, h1);
        ((__half2*)outh)[2 * idx + 1] = __halves2half2(h2, h3);
        __half l0 = __float2half_rn(v.x - __half2float(h0));
        __half l1 = __float2half_rn(v.y - __half2float(h1));
        __half l2 = __float2half_rn(v.z - __half2float(h2));
        __half l3 = __float2half_rn(v.w - __half2float(h3));
        ((__half2*)outl)[2 * idx]     = __halves2half2(l0, l1);
        ((__half2*)outl)[2 * idx + 1] = __halves2half2(l2, l3);
    }
}

// ===========================================================================
// Zero the stats accumulator
// ===========================================================================
__global__ void zero_stats_kernel() {
    int idx = blockIdx.x * blockDim.x + threadIdx.x;
    if (idx < NHEADS_TOTAL * STATS_PER_HEAD) g_stats[idx] = 0.0f;
}

// ===========================================================================
// Stats: per head (b,h) accumulate C[i][j]=sum_t q_i k_j, Sq, Sk, Sqq, Skk
// ===========================================================================
#define TSPLIT 8
#define TCHUNK (T_LEN / TSPLIT)   // 1024

__global__ __launch_bounds__(256) void stats_kernel(const float* __restrict__ qkv) {
    const int head = blockIdx.y;
    const int b = head >> 4, h = head & 15;
    const int tid = threadIdx.x;

    __shared__ float qs[16][HD];
    __shared__ float ks[16][HD];

    const float* qbase = qkv + (size_t)b * QKV_LD + h * HD;
    const float* kbase = qbase + D_MODEL;

    float acc[4][4];
    #pragma unroll
    for (int i = 0; i < 4; i++)
        #pragma unroll
        for (int j = 0; j < 4; j++) acc[i][j] = 0.0f;
    float sq = 0.f, sqq = 0.f, sk = 0.f, skk = 0.f;

    const int i0 = (tid >> 4) * 4, j0 = (tid & 15) * 4;
    const int lrow = tid >> 4;
    const int lcol = (tid & 15) * 4;

    const int tstart = blockIdx.x * TCHUNK;
    for (int t0 = tstart; t0 < tstart + TCHUNK; t0 += 16) {
        size_t grow = (size_t)(t0 + lrow) * BATCH * QKV_LD;
        *(float4*)&qs[lrow][lcol] = *(const float4*)(qbase + grow + lcol);
        *(float4*)&ks[lrow][lcol] = *(const float4*)(kbase + grow + lcol);
        __syncthreads();

        if (tid < 64) {
            #pragma unroll
            for (int tt = 0; tt < 16; tt++) {
                float v = qs[tt][tid]; sq += v; sqq += v * v;
            }
        } else if (tid < 128) {
            int j = tid - 64;
            #pragma unroll
            for (int tt = 0; tt < 16; tt++) {
                float v = ks[tt][j]; sk += v; skk += v * v;
            }
        }
        #pragma unroll
        for (int tt = 0; tt < 16; tt++) {
            float4 qa = *(const float4*)&qs[tt][i0];
            float4 kb = *(const float4*)&ks[tt][j0];
            float qv[4] = {qa.x, qa.y, qa.z, qa.w};
            float kv[4] = {kb.x, kb.y, kb.z, kb.w};
            #pragma unroll
            for (int ii = 0; ii < 4; ii++)
                #pragma unroll
                for (int jj = 0; jj < 4; jj++)
                    acc[ii][jj] += qv[ii] * kv[jj];
        }
        __syncthreads();
    }

    float* st = g_stats + (size_t)head * STATS_PER_HEAD;
    #pragma unroll
    for (int ii = 0; ii < 4; ii++)
        #pragma unroll
        for (int jj = 0; jj < 4; jj++)
            atomicAdd(&st[(i0 + ii) * HD + (j0 + jj)], acc[ii][jj]);
    if (tid < 64) {
        atomicAdd(&st[4096 + tid], sq);
        atomicAdd(&st[4224 + tid], sqq);
    } else if (tid < 128) {
        atomicAdd(&st[4160 + (tid - 64)], sk);
        atomicAdd(&st[4288 + (tid - 64)], skk);
    }
}

// ===========================================================================
// Corr: corr = softmax_i(clip(cov/sqrt(sx*sy),0,1))
// ===========================================================================
__global__ __launch_bounds__(256) void corr_kernel() {
    const int head = blockIdx.x;
    const int tid = threadIdx.x;
    __shared__ float sc[HD][HD + 1];
    __shared__ float mq[HD], mk[HD], isx[HD], isy[HD];

    const float* st = g_stats + (size_t)head * STATS_PER_HEAD;
    const float invT = 1.0f / (float)T_LEN;

    if (tid < 64) {
        float s = st[4096 + tid], s2 = st[4224 + tid];
        mq[tid] = s;
        isx[tid] = rsqrtf(s2 - s * s * invT);
    } else if (tid < 128) {
        int j = tid - 64;
        float s = st[4160 + j], s2 = st[4288 + j];
        mk[j] = s;
        isy[j] = rsqrtf(s2 - s * s * invT);
    }
    __syncthreads();

    for (int idx = tid; idx < HD * HD; idx += 256) {
        int i = idx >> 6, j = idx & 63;
        float cov = st[idx] - mq[i] * mk[j] * invT;
        float c = cov * isx[i] * isy[j];
        c = fminf(fmaxf(c, 0.0f), 1.0f);
        sc[i][j] = c;
    }
    __syncthreads();

    if (tid < 64) {
        int j = tid;
        float mx = -1e30f;
        #pragma unroll 4
        for (int i = 0; i < HD; i++) mx = fmaxf(mx, sc[i][j]);
        float sum = 0.f;
        #pragma unroll 4
        for (int i = 0; i < HD; i++) {
            float e = expf(sc[i][j] - mx);
            sc[i][j] = e; sum += e;
        }
        float inv = 1.0f / sum;
        #pragma unroll 4
        for (int i = 0; i < HD; i++) sc[i][j] *= inv;
    }
    __syncthreads();

    for (int idx = tid; idx < HD * HD; idx += 256)
        g_corr[(size_t)head * HD * HD + idx] = sc[idx >> 6][idx & 63];
}

// ===========================================================================
// Meff: Meff^T[b][o][h*64+d] = sum_e corr[b,h][d][e] * Wout[o][h*64+e]
// Emitted directly as fp16 hi/lo split for GEMM2's B operand.
// ===========================================================================
__global__ __launch_bounds__(256) void meff_kernel(const float* __restrict__ Wout) {
    const int head = blockIdx.x;
    const int b = head >> 4, h = head & 15;
    const int tid = threadIdx.x;
    __shared__ float sc[HD][HD + 1];

    for (int idx = tid; idx < HD * HD; idx += 256)
        sc[idx >> 6][idx & 63] = g_corr[(size_t)head * HD * HD + idx];
    __syncthreads();

    const size_t mbase = (size_t)b * D_MODEL * D_MODEL + h * HD;
    const float* Wb = Wout + h * HD;

    for (int idx = tid; idx < D_MODEL * HD; idx += 256) {
        int o = idx >> 6, d = idx & 63;
        const float* wrow = Wb + (size_t)o * D_MODEL;
        float s = 0.f;
        #pragma unroll
        for (int e = 0; e < HD; e++) s += sc[d][e] * wrow[e];
        __half hh = __float2half_rn(s);
        __half hl = __float2half_rn(s - __half2float(hh));
        g_mh[mbase + (size_t)o * D_MODEL + d] = hh;
        g_ml[mbase + (size_t)o * D_MODEL + d] = hl;
    }
}

// ===========================================================================
// Launch
// ===========================================================================
extern "C" void kernel_launch(void* const* d_in, const int* in_sizes, int n_in,
                              void* d_out, int out_size) {
    const float* query = (const float*)d_in[0];
    const float* Wqkv  = (const float*)d_in[1];
    const float* bqkv  = (const float*)d_in[2];
    const float* Wout  = (const float*)d_in[3];
    const float* bout  = (const float*)d_in[4];
    float* out = (float*)d_out;

    void* p;
    cudaGetSymbolAddress(&p, g_qkv);  float*  qkv = (float*)p;
    cudaGetSymbolAddress(&p, g_qh);   __half* qh  = (__half*)p;
    cudaGetSymbolAddress(&p, g_wh);   __half* wh  = (__half*)p;
    cudaGetSymbolAddress(&p, g_wl);   __half* wl  = (__half*)p;
    cudaGetSymbolAddress(&p, g_vh);   __half* vh  = (__half*)p;
    cudaGetSymbolAddress(&p, g_vl);   __half* vl  = (__half*)p;
    cudaGetSymbolAddress(&p, g_mh);   __half* mh  = (__half*)p;
    cudaGetSymbolAddress(&p, g_ml);   __half* ml  = (__half*)p;

    cudaFuncSetAttribute(gemm_fp16_kernel,
                         cudaFuncAttributeMaxDynamicSharedMemorySize, SMEMB);

    // 0. zero stats accumulator
    {
        int total = NHEADS_TOTAL * STATS_PER_HEAD;
        zero_stats_kernel<<<(total + 1023) / 1024, 1024>>>();
    }

    // 1. converters: query -> fp16, Wqkv -> fp16 hi/lo
    {
        int n4q = NROWS * D_MODEL / 4;      // 8388608
        conv_half_kernel<<<n4q / 256, 256>>>(query, qh, n4q);
        int n4w = QKV_LD * D_MODEL / 4;     // 786432
        conv_split_kernel<<<n4w / 256, 256>>>(Wqkv, wh, wl, n4w);
    }

    // 2. GEMM1: qkv = query @ Wqkv^T + bqkv. q,k -> fp32 g_qkv; v -> fp16 split.
    gemm_fp16_kernel<<<dim3(QKV_LD / BN, NROWS / BM, 1), 256, SMEMB>>>(
        qh, D_MODEL, 0,
        wh, wl, D_MODEL, 0,
        bqkv,
        qkv, QKV_LD, 0,
        vh, vl,
        D_MODEL);

    // 3. per-head stats
    stats_kernel<<<dim3(TSPLIT, NHEADS_TOTAL), 256>>>(qkv);

    // 4. correlation + softmax
    corr_kernel<<<NHEADS_TOTAL, 256>>>();

    // 5. Meff_b = blockdiag(corr_b) @ Wout^T  (fp16 hi/lo)
    meff_kernel<<<NHEADS_TOTAL, 256>>>(Wout);

    // 6. out = v @ Meff_b^T + bout   per batch z
    gemm_fp16_kernel<<<dim3(D_MODEL / BN, T_LEN / BM, BATCH), 256, SMEMB>>>(
        vh, BATCH * D_MODEL, D_MODEL,
        mh, ml, D_MODEL, (long long)D_MODEL * D_MODEL,
        bout,
        out, BATCH * D_MODEL, D_MODEL,
        nullptr, nullptr,
        D_MODEL);
}

// round 6
// speedup vs baseline: 4.2266x; 1.3967x over previous
#include <cuda_runtime.h>
#include <cuda_fp16.h>
#include <cstdint>

// Problem constants
#define T_LEN   8192
#define BATCH   4
#define D_MODEL 1024
#define NHEAD   16
#define HD      64
#define QKV_LD  (3 * D_MODEL)        // 3072
#define NROWS   (T_LEN * BATCH)      // 32768
#define NHEADS_TOTAL (BATCH * NHEAD) // 64
#define STATS_PER_HEAD 4352

// Scratch (device globals: allocation-free)
__device__ float  g_qkv[(size_t)NROWS * QKV_LD];                 // 384 MB (q,k used)
__device__ __half g_qh[(size_t)NROWS * D_MODEL];                 // 64 MB  query fp16
__device__ __half g_wh[(size_t)QKV_LD * D_MODEL];                // 6 MB   Wqkv fp16
__device__ __half g_vh[(size_t)NROWS * D_MODEL];                 // 64 MB  v fp16
__device__ __half g_mh[(size_t)BATCH * D_MODEL * D_MODEL];       // 8 MB  Meff fp16
__device__ float  g_stats[NHEADS_TOTAL * STATS_PER_HEAD];
__device__ float  g_corr[NHEADS_TOTAL * HD * HD];

// ===========================================================================
// helpers
// ===========================================================================
__device__ __forceinline__ uint32_t smem_to_u32(const void* p) {
    uint32_t a;
    asm("{ .reg .u64 t; cvta.to.shared.u64 t, %1; cvt.u32.u64 %0, t; }"
        : "=r"(a) : "l"(p));
    return a;
}

__device__ __forceinline__ void ldsm4(uint32_t (&r)[4], uint32_t addr) {
    asm volatile("ldmatrix.sync.aligned.m8n8.x4.shared.b16 {%0,%1,%2,%3}, [%4];"
        : "=r"(r[0]), "=r"(r[1]), "=r"(r[2]), "=r"(r[3]) : "r"(addr));
}

__device__ __forceinline__ void mma16816(float (&c)[4], const uint32_t (&a)[4],
                                         uint32_t b0, uint32_t b1) {
    asm volatile(
        "mma.sync.aligned.m16n8k16.row.col.f32.f16.f16.f32 "
        "{%0,%1,%2,%3}, {%4,%5,%6,%7}, {%8,%9}, {%0,%1,%2,%3};"
        : "+f"(c[0]), "+f"(c[1]), "+f"(c[2]), "+f"(c[3])
        : "r"(a[0]), "r"(a[1]), "r"(a[2]), "r"(a[3]), "r"(b0), "r"(b1));
}

#define CP_COMMIT() asm volatile("cp.async.commit_group;" ::: "memory")
#define CP16(dst, src) \
    asm volatile("cp.async.cg.shared.global [%0], [%1], 16;" \
        :: "r"(dst), "l"(src) : "memory")

// ===========================================================================
// fp16 single-pass HMMA GEMM (NT): C[m,n] = sum_k A[m,k]*B[n,k] + bias[n]
// 256x128x32 CTA tile, 8 warps (4x2), warp tile 64x64.
// 4-stage cp.async pipeline. smem rows 80B (conflict-free ldmatrix).
// Optional epilogue: columns >= 2048 written as fp16 (v output).
// ===========================================================================
#define BM 256
#define BN 128
#define BK 32
#define ROWB 80
#define A_TILEB (256 * ROWB)    // 20480
#define B_TILEB (128 * ROWB)    // 10240
#define OFF_A  0
#define OFF_B  A_TILEB
#define STAGEB (A_TILEB + B_TILEB)      // 30720
#define NSTAGE 4
#define SMEMB (NSTAGE * STAGEB)         // 122880

__global__ void __launch_bounds__(256, 1) gemm_fp16_kernel(
    const __half* __restrict__ Ah, int strideA, long long batchA,
    const __half* __restrict__ Bh, int strideB, long long batchB,
    const float* __restrict__ bias,
    float* __restrict__ C, int strideC, long long batchC,
    __half* __restrict__ Vh,
    int K)
{
    extern __shared__ char smem[];
    const uint32_t sb = smem_to_u32(smem);
    const int tid = threadIdx.x;
    const int lane = tid & 31;
    const int wid = tid >> 5;
    const int wm = (wid >> 1) * 64;   // 0,64,128,192
    const int wn = (wid & 1) * 64;    // 0,64
    const int z = blockIdx.z;

    const __half* Ab = Ah + (size_t)blockIdx.y * BM * strideA + (size_t)z * batchA;
    const __half* Bb = Bh + (size_t)blockIdx.x * BN * strideB + (size_t)z * batchB;

    float acc[4][8][4];
    #pragma unroll
    for (int mt = 0; mt < 4; mt++)
        #pragma unroll
        for (int nt = 0; nt < 8; nt++)
            #pragma unroll
            for (int r = 0; r < 4; r++) acc[mt][nt][r] = 0.0f;

    const int NKT = K / BK;

    // 6 x 16B cp.async per thread per stage:
    // i<4 -> A (1024 chunks: 256 rows x 4), i=4,5 -> B (512 chunks)
    #define ISSUE_STAGE(kt, buf) do { \
        const uint32_t sbase = sb + (buf) * STAGEB; \
        _Pragma("unroll") \
        for (int i = 0; i < 6; i++) { \
            const int ci = i * 256 + tid; \
            const __half* src; uint32_t dst; \
            if (i < 4) { \
                const int r_ = ci >> 2, c_ = ci & 3; \
                src = Ab + (size_t)r_ * strideA + (kt) * BK + c_ * 8; \
                dst = sbase + OFF_A + r_ * ROWB + c_ * 16; \
            } else { \
                const int j_ = ci - 1024, r_ = j_ >> 2, c_ = j_ & 3; \
                src = Bb + (size_t)r_ * strideB + (kt) * BK + c_ * 8; \
                dst = sbase + OFF_B + r_ * ROWB + c_ * 16; \
            } \
            CP16(dst, src); \
        } \
    } while (0)

    ISSUE_STAGE(0, 0); CP_COMMIT();
    ISSUE_STAGE(1, 1); CP_COMMIT();
    ISSUE_STAGE(2, 2); CP_COMMIT();

    // frag address components (constant per thread)
    const uint32_t a_off = (uint32_t)((lane & 15) * ROWB + (lane >> 4) * 16);
    const uint32_t b_row = (uint32_t)((lane & 7) + ((lane >> 4) << 3));
    const uint32_t b_off = (uint32_t)(b_row * ROWB + ((lane >> 3) & 1) * 16);

    for (int kt = 0; kt < NKT; kt++) {
        asm volatile("cp.async.wait_group 2;" ::: "memory");
        __syncthreads();

        if (kt + 3 < NKT) { ISSUE_STAGE(kt + 3, (kt + 3) % NSTAGE); CP_COMMIT(); }

        const uint32_t base = sb + (kt % NSTAGE) * STAGEB;
        #pragma unroll
        for (int kk = 0; kk < 2; kk++) {
            const uint32_t koff = kk * 32;
            uint32_t a[4][4];
            #pragma unroll
            for (int mt = 0; mt < 4; mt++)
                ldsm4(a[mt], base + OFF_A + (wm + mt * 16) * ROWB + a_off + koff);
            #pragma unroll
            for (int ng = 0; ng < 4; ng++) {
                uint32_t bh[4];
                ldsm4(bh, base + OFF_B + (wn + ng * 16) * ROWB + b_off + koff);
                #pragma unroll
                for (int mt = 0; mt < 4; mt++) {
                    mma16816(acc[mt][2*ng],   a[mt], bh[0], bh[1]);
                    mma16816(acc[mt][2*ng+1], a[mt], bh[2], bh[3]);
                }
            }
        }
    }

    // ---- epilogue ----
    const int rbase = blockIdx.y * BM + wm + (lane >> 2);
    const int cbase = blockIdx.x * BN + wn + (lane & 3) * 2;
    float* Cz = C + (size_t)z * batchC;
    #pragma unroll
    for (int mt = 0; mt < 4; mt++) {
        #pragma unroll
        for (int nt = 0; nt < 8; nt++) {
            const int row = rbase + mt * 16;
            const int col = cbase + nt * 8;
            const float b0 = bias[col], b1 = bias[col + 1];
            const float v0 = acc[mt][nt][0] + b0, v1 = acc[mt][nt][1] + b1;
            const float v2 = acc[mt][nt][2] + b0, v3 = acc[mt][nt][3] + b1;
            if (Vh != nullptr && col >= 2048) {
                const int vc = col - 2048;
                *(__half2*)(Vh + (size_t)row * D_MODEL + vc)       = __floats2half2_rn(v0, v1);
                *(__half2*)(Vh + (size_t)(row + 8) * D_MODEL + vc) = __floats2half2_rn(v2, v3);
            } else {
                float2 o0, o1;
                o0.x = v0; o0.y = v1; o1.x = v2; o1.y = v3;
                *(float2*)(Cz + (size_t)row * strideC + col) = o0;
                *(float2*)(Cz + (size_t)(row + 8) * strideC + col) = o1;
            }
        }
    }
}

// ===========================================================================
// Converter: fp32 -> fp16
// ===========================================================================
__global__ void conv_half_kernel(const float* __restrict__ in,
                                 __half* __restrict__ outh, int n4) {
    int idx = blockIdx.x * blockDim.x + threadIdx.x;
    if (idx < n4) {
        float4 v = ((const float4*)in)[idx];
        ((__half2*)outh)[2 * idx]     = __floats2half2_rn(v.x, v.y);
        ((__half2*)outh)[2 * idx + 1] = __floats2half2_rn(v.z, v.w);
    }
}

// ===========================================================================
// Zero the stats accumulator
// ===========================================================================
__global__ void zero_stats_kernel() {
    int idx = blockIdx.x * blockDim.x + threadIdx.x;
    if (idx < NHEADS_TOTAL * STATS_PER_HEAD) g_stats[idx] = 0.0f;
}

// ===========================================================================
// Stats: per head (b,h) accumulate C[i][j]=sum_t q_i k_j, Sq, Sk, Sqq, Skk
// ===========================================================================
#define TSPLIT 8
#define TCHUNK (T_LEN / TSPLIT)   // 1024

__global__ __launch_bounds__(256) void stats_kernel(const float* __restrict__ qkv) {
    const int head = blockIdx.y;
    const int b = head >> 4, h = head & 15;
    const int tid = threadIdx.x;

    __shared__ float qs[16][HD];
    __shared__ float ks[16][HD];

    const float* qbase = qkv + (size_t)b * QKV_LD + h * HD;
    const float* kbase = qbase + D_MODEL;

    float acc[4][4];
    #pragma unroll
    for (int i = 0; i < 4; i++)
        #pragma unroll
        for (int j = 0; j < 4; j++) acc[i][j] = 0.0f;
    float sq = 0.f, sqq = 0.f, sk = 0.f, skk = 0.f;

    const int i0 = (tid >> 4) * 4, j0 = (tid & 15) * 4;
    const int lrow = tid >> 4;
    const int lcol = (tid & 15) * 4;

    const int tstart = blockIdx.x * TCHUNK;
    for (int t0 = tstart; t0 < tstart + TCHUNK; t0 += 16) {
        size_t grow = (size_t)(t0 + lrow) * BATCH * QKV_LD;
        *(float4*)&qs[lrow][lcol] = *(const float4*)(qbase + grow + lcol);
        *(float4*)&ks[lrow][lcol] = *(const float4*)(kbase + grow + lcol);
        __syncthreads();

        if (tid < 64) {
            #pragma unroll
            for (int tt = 0; tt < 16; tt++) {
                float v = qs[tt][tid]; sq += v; sqq += v * v;
            }
        } else if (tid < 128) {
            int j = tid - 64;
            #pragma unroll
            for (int tt = 0; tt < 16; tt++) {
                float v = ks[tt][j]; sk += v; skk += v * v;
            }
        }
        #pragma unroll
        for (int tt = 0; tt < 16; tt++) {
            float4 qa = *(const float4*)&qs[tt][i0];
            float4 kb = *(const float4*)&ks[tt][j0];
            float qv[4] = {qa.x, qa.y, qa.z, qa.w};
            float kv[4] = {kb.x, kb.y, kb.z, kb.w};
            #pragma unroll
            for (int ii = 0; ii < 4; ii++)
                #pragma unroll
                for (int jj = 0; jj < 4; jj++)
                    acc[ii][jj] += qv[ii] * kv[jj];
        }
        __syncthreads();
    }

    float* st = g_stats + (size_t)head * STATS_PER_HEAD;
    #pragma unroll
    for (int ii = 0; ii < 4; ii++)
        #pragma unroll
        for (int jj = 0; jj < 4; jj++)
            atomicAdd(&st[(i0 + ii) * HD + (j0 + jj)], acc[ii][jj]);
    if (tid < 64) {
        atomicAdd(&st[4096 + tid], sq);
        atomicAdd(&st[4224 + tid], sqq);
    } else if (tid < 128) {
        atomicAdd(&st[4160 + (tid - 64)], sk);
        atomicAdd(&st[4288 + (tid - 64)], skk);
    }
}

// ===========================================================================
// Corr: corr = softmax_i(clip(cov/sqrt(sx*sy),0,1))
// ===========================================================================
__global__ __launch_bounds__(256) void corr_kernel() {
    const int head = blockIdx.x;
    const int tid = threadIdx.x;
    __shared__ float sc[HD][HD + 1];
    __shared__ float mq[HD], mk[HD], isx[HD], isy[HD];

    const float* st = g_stats + (size_t)head * STATS_PER_HEAD;
    const float invT = 1.0f / (float)T_LEN;

    if (tid < 64) {
        float s = st[4096 + tid], s2 = st[4224 + tid];
        mq[tid] = s;
        isx[tid] = rsqrtf(s2 - s * s * invT);
    } else if (tid < 128) {
        int j = tid - 64;
        float s = st[4160 + j], s2 = st[4288 + j];
        mk[j] = s;
        isy[j] = rsqrtf(s2 - s * s * invT);
    }
    __syncthreads();

    for (int idx = tid; idx < HD * HD; idx += 256) {
        int i = idx >> 6, j = idx & 63;
        float cov = st[idx] - mq[i] * mk[j] * invT;
        float c = cov * isx[i] * isy[j];
        c = fminf(fmaxf(c, 0.0f), 1.0f);
        sc[i][j] = c;
    }
    __syncthreads();

    if (tid < 64) {
        int j = tid;
        float mx = -1e30f;
        #pragma unroll 4
        for (int i = 0; i < HD; i++) mx = fmaxf(mx, sc[i][j]);
        float sum = 0.f;
        #pragma unroll 4
        for (int i = 0; i < HD; i++) {
            float e = expf(sc[i][j] - mx);
            sc[i][j] = e; sum += e;
        }
        float inv = 1.0f / sum;
        #pragma unroll 4
        for (int i = 0; i < HD; i++) sc[i][j] *= inv;
    }
    __syncthreads();

    for (int idx = tid; idx < HD * HD; idx += 256)
        g_corr[(size_t)head * HD * HD + idx] = sc[idx >> 6][idx & 63];
}

// ===========================================================================
// Meff: Meff^T[b][o][h*64+d] = sum_e corr[b,h][d][e] * Wout[o][h*64+e]
// Emitted directly as fp16 for GEMM2's B operand.
// ===========================================================================
__global__ __launch_bounds__(256) void meff_kernel(const float* __restrict__ Wout) {
    const int head = blockIdx.x;
    const int b = head >> 4, h = head & 15;
    const int tid = threadIdx.x;
    __shared__ float sc[HD][HD + 1];

    for (int idx = tid; idx < HD * HD; idx += 256)
        sc[idx >> 6][idx & 63] = g_corr[(size_t)head * HD * HD + idx];
    __syncthreads();

    const size_t mbase = (size_t)b * D_MODEL * D_MODEL + h * HD;
    const float* Wb = Wout + h * HD;

    for (int idx = tid; idx < D_MODEL * HD; idx += 256) {
        int o = idx >> 6, d = idx & 63;
        const float* wrow = Wb + (size_t)o * D_MODEL;
        float s = 0.f;
        #pragma unroll
        for (int e = 0; e < HD; e++) s += sc[d][e] * wrow[e];
        g_mh[mbase + (size_t)o * D_MODEL + d] = __float2half_rn(s);
    }
}

// ===========================================================================
// Launch
// ===========================================================================
extern "C" void kernel_launch(void* const* d_in, const int* in_sizes, int n_in,
                              void* d_out, int out_size) {
    const float* query = (const float*)d_in[0];
    const float* Wqkv  = (const float*)d_in[1];
    const float* bqkv  = (const float*)d_in[2];
    const float* Wout  = (const float*)d_in[3];
    const float* bout  = (const float*)d_in[4];
    float* out = (float*)d_out;

    void* p;
    cudaGetSymbolAddress(&p, g_qkv);  float*  qkv = (float*)p;
    cudaGetSymbolAddress(&p, g_qh);   __half* qh  = (__half*)p;
    cudaGetSymbolAddress(&p, g_wh);   __half* wh  = (__half*)p;
    cudaGetSymbolAddress(&p, g_vh);   __half* vh  = (__half*)p;
    cudaGetSymbolAddress(&p, g_mh);   __half* mh  = (__half*)p;

    cudaFuncSetAttribute(gemm_fp16_kernel,
                         cudaFuncAttributeMaxDynamicSharedMemorySize, SMEMB);

    // 0. zero stats accumulator
    {
        int total = NHEADS_TOTAL * STATS_PER_HEAD;
        zero_stats_kernel<<<(total + 1023) / 1024, 1024>>>();
    }

    // 1. converters: query -> fp16, Wqkv -> fp16
    {
        int n4q = NROWS * D_MODEL / 4;      // 8388608
        conv_half_kernel<<<n4q / 256, 256>>>(query, qh, n4q);
        int n4w = QKV_LD * D_MODEL / 4;     // 786432
        conv_half_kernel<<<n4w / 256, 256>>>(Wqkv, wh, n4w);
    }

    // 2. GEMM1: qkv = query @ Wqkv^T + bqkv. q,k -> fp32 g_qkv; v -> fp16.
    gemm_fp16_kernel<<<dim3(QKV_LD / BN, NROWS / BM, 1), 256, SMEMB>>>(
        qh, D_MODEL, 0,
        wh, D_MODEL, 0,
        bqkv,
        qkv, QKV_LD, 0,
        vh,
        D_MODEL);

    // 3. per-head stats
    stats_kernel<<<dim3(TSPLIT, NHEADS_TOTAL), 256>>>(qkv);

    // 4. correlation + softmax
    corr_kernel<<<NHEADS_TOTAL, 256>>>();

    // 5. Meff_b = blockdiag(corr_b) @ Wout^T  (fp16)
    meff_kernel<<<NHEADS_TOTAL, 256>>>(Wout);

    // 6. out = v @ Meff_b^T + bout   per batch z
    gemm_fp16_kernel<<<dim3(D_MODEL / BN, T_LEN / BM, BATCH), 256, SMEMB>>>(
        vh, BATCH * D_MODEL, D_MODEL,
        mh, D_MODEL, (long long)D_MODEL * D_MODEL,
        bout,
        out, BATCH * D_MODEL, D_MODEL,
        nullptr,
        D_MODEL);
}